// round 1
// baseline (speedup 1.0000x reference)
#include <cuda_runtime.h>

#define NN 50000
#define EE 800000
#define HH 8
#define HD 128
#define CCOLS 40

// ---------------- scratch (static device arrays — no runtime allocation) ----
__device__ float g_hp[NN * HD];    // per-layer projected features
__device__ float g_hbuf[NN * HD];  // layer output / next-layer input
__device__ float g_el[NN * HH];
__device__ float g_er[NN * HH];
__device__ int   g_rowptr[NN + 1];
__device__ int   g_wr[NN];
__device__ int   g_csrc[EE];       // src node id per incoming edge, CSR by dst

// ---------------- CSR build ------------------------------------------------
__global__ void zero_wr_kernel() {
    int i = blockIdx.x * blockDim.x + threadIdx.x;
    if (i < NN) g_wr[i] = 0;
}

__global__ void count_deg_kernel(const int* __restrict__ dst) {
    int e = blockIdx.x * blockDim.x + threadIdx.x;
    if (e < EE) atomicAdd(&g_wr[dst[e]], 1);
}

// single-block exclusive scan over g_wr -> g_rowptr (and g_wr := exclusive)
__global__ void scan_deg_kernel() {
    __shared__ int wsum[32];
    __shared__ int carry_sh;
    __shared__ int total_sh;
    int t = threadIdx.x;
    int lane = t & 31, wid = t >> 5;
    if (t == 0) carry_sh = 0;
    __syncthreads();
    for (int base = 0; base < NN; base += 1024) {
        int i = base + t;
        int v = (i < NN) ? g_wr[i] : 0;
        int x = v;
        #pragma unroll
        for (int off = 1; off < 32; off <<= 1) {
            int y = __shfl_up_sync(0xFFFFFFFFu, x, off);
            if (lane >= off) x += y;
        }
        if (lane == 31) wsum[wid] = x;
        __syncthreads();
        if (wid == 0) {
            int w = wsum[lane];
            int xw = w;
            #pragma unroll
            for (int off = 1; off < 32; off <<= 1) {
                int y = __shfl_up_sync(0xFFFFFFFFu, xw, off);
                if (lane >= off) xw += y;
            }
            wsum[lane] = xw - w;          // exclusive warp offset
            if (lane == 31) total_sh = xw; // chunk total
        }
        __syncthreads();
        int excl = carry_sh + wsum[wid] + (x - v);
        if (i < NN) { g_rowptr[i] = excl; g_wr[i] = excl; }
        __syncthreads();
        if (t == 0) carry_sh += total_sh;
        __syncthreads();
    }
    if (t == 0) g_rowptr[NN] = carry_sh;
}

__global__ void fill_csr_kernel(const int* __restrict__ src, const int* __restrict__ dst) {
    int e = blockIdx.x * blockDim.x + threadIdx.x;
    if (e < EE) {
        int p = atomicAdd(&g_wr[dst[e]], 1);
        g_csrc[p] = src[e];
    }
}

// ---------------- GEMM: C[M,128] = A[M,128] @ W[128,128] --------------------
// block: 256 threads, 64 rows x 128 cols, 8x4 register tile
__global__ __launch_bounds__(256) void gemm_nodes_kernel(
    const float* __restrict__ A, const float* __restrict__ W, float* __restrict__ C) {
    __shared__ float Ash[32][68];    // A tile transposed: [k][row]
    __shared__ float Wsh[32][128];
    int tid = threadIdx.x;
    int tx = tid & 31;   // cols 4*tx .. 4*tx+3
    int ty = tid >> 5;   // rows ty*8 .. ty*8+7
    int row0 = blockIdx.x << 6;
    float acc[8][4];
    #pragma unroll
    for (int r = 0; r < 8; r++)
        #pragma unroll
        for (int c = 0; c < 4; c++) acc[r][c] = 0.f;

    for (int kc = 0; kc < 128; kc += 32) {
        #pragma unroll
        for (int i = 0; i < 8; i++) {
            int idx = tid + (i << 8);
            int r = idx >> 5;
            int k = idx & 31;
            int gr = row0 + r;
            Ash[k][r] = (gr < NN) ? A[gr * 128 + kc + k] : 0.f;
        }
        #pragma unroll
        for (int i = 0; i < 16; i++) {
            int idx = tid + (i << 8);
            int k = idx >> 7;
            int c = idx & 127;
            Wsh[k][c] = W[(kc + k) * 128 + c];
        }
        __syncthreads();
        #pragma unroll
        for (int k = 0; k < 32; k++) {
            float4 a0 = *(const float4*)&Ash[k][ty * 8];
            float4 a1 = *(const float4*)&Ash[k][ty * 8 + 4];
            float4 b  = *(const float4*)&Wsh[k][tx * 4];
            float av[8] = {a0.x, a0.y, a0.z, a0.w, a1.x, a1.y, a1.z, a1.w};
            float bv[4] = {b.x, b.y, b.z, b.w};
            #pragma unroll
            for (int r = 0; r < 8; r++)
                #pragma unroll
                for (int c = 0; c < 4; c++)
                    acc[r][c] = fmaf(av[r], bv[c], acc[r][c]);
        }
        __syncthreads();
    }
    #pragma unroll
    for (int r = 0; r < 8; r++) {
        int gr = row0 + ty * 8 + r;
        if (gr < NN) {
            float4 o = make_float4(acc[r][0], acc[r][1], acc[r][2], acc[r][3]);
            *(float4*)&C[gr * 128 + tx * 4] = o;
        }
    }
}

// ---------------- per-node attention logits --------------------------------
__global__ __launch_bounds__(128) void elr_kernel(
    const float* __restrict__ hp, const float* __restrict__ al, const float* __restrict__ ar) {
    int n = blockIdx.x;
    int t = threadIdx.x;  // 128; t = h*16 + d
    float v = hp[n * 128 + t];
    float pl = v * al[t];
    float pr = v * ar[t];
    #pragma unroll
    for (int off = 8; off >= 1; off >>= 1) {
        pl += __shfl_down_sync(0xFFFFFFFFu, pl, off, 16);
        pr += __shfl_down_sync(0xFFFFFFFFu, pr, off, 16);
    }
    if ((t & 15) == 0) {
        g_el[n * 8 + (t >> 4)] = pl;
        g_er[n * 8 + (t >> 4)] = pr;
    }
}

// ---------------- fused: edge-softmax aggregate + bias + LN + ReLU ----------
// one block (128 threads) per dst node; single pass over incoming edges.
// softmax max-shift omitted: logits are bounded (|e| < ~5) so exp is safe.
__global__ __launch_bounds__(128) void gat_agg_kernel(
    const float* __restrict__ hp,
    const float* __restrict__ bias, const float* __restrict__ gamma,
    const float* __restrict__ beta, float* __restrict__ hout) {
    int n = blockIdx.x;
    int t = threadIdx.x;        // t = h*16 + d
    int h = t >> 4;
    float er_h = g_er[n * 8 + h];
    int beg = g_rowptr[n];
    int end = g_rowptr[n + 1];
    float acc = 0.f, s = 0.f;
    for (int j = beg; j < end; j++) {
        int src = g_csrc[j];
        float e = g_el[src * 8 + h] + er_h;
        e = (e > 0.f) ? e : 0.2f * e;      // leaky relu, slope 0.2
        float w = __expf(e);
        s += w;
        acc = fmaf(w, hp[src * 128 + t], acc);
    }
    float out = acc / (s + 1e-16f) + bias[t];

    // LayerNorm over 128 channels
    __shared__ float red1[4], red2[4];
    int lane = t & 31, wid = t >> 5;
    float sum = out;
    #pragma unroll
    for (int off = 16; off >= 1; off >>= 1) sum += __shfl_down_sync(0xFFFFFFFFu, sum, off);
    if (lane == 0) red1[wid] = sum;
    __syncthreads();
    float mu = (red1[0] + red1[1] + red1[2] + red1[3]) * 0.0078125f;
    float d = out - mu;
    float sq = d * d;
    #pragma unroll
    for (int off = 16; off >= 1; off >>= 1) sq += __shfl_down_sync(0xFFFFFFFFu, sq, off);
    if (lane == 0) red2[wid] = sq;
    __syncthreads();
    float var = (red2[0] + red2[1] + red2[2] + red2[3]) * 0.0078125f;
    float y = d * rsqrtf(var + 1e-5f) * gamma[t] + beta[t];
    hout[n * 128 + t] = fmaxf(y, 0.f);
}

// ---------------- final projection: out[N,40] = h[N,128] @ Wp + bp ----------
// block: 160 threads = 16 node-threads (4 nodes each) x 10 col-threads (4 cols each)
__global__ __launch_bounds__(160) void pred_kernel(
    const float* __restrict__ hfeat, const float* __restrict__ Wp,
    const float* __restrict__ bp, float* __restrict__ out) {
    __shared__ float Hs[64][68];   // [k][node], K-chunk 64
    __shared__ float Wsh[64][40];
    int tid = threadIdx.x;
    int ci = tid % 10;      // cols 4*ci .. 4*ci+3
    int j  = tid / 10;      // nodes j*4 .. j*4+3
    int n0 = blockIdx.x << 6;
    float acc[4][4];
    #pragma unroll
    for (int r = 0; r < 4; r++)
        #pragma unroll
        for (int c = 0; c < 4; c++) acc[r][c] = 0.f;

    for (int kc = 0; kc < 128; kc += 64) {
        for (int idx = tid; idx < 64 * 64; idx += 160) {
            int n = idx >> 6;
            int k = idx & 63;
            int gn = n0 + n;
            Hs[k][n] = (gn < NN) ? hfeat[gn * 128 + kc + k] : 0.f;
        }
        for (int idx = tid; idx < 64 * 40; idx += 160) {
            int k = idx / 40;
            int c = idx - k * 40;
            Wsh[k][c] = Wp[(kc + k) * 40 + c];
        }
        __syncthreads();
        #pragma unroll
        for (int k = 0; k < 64; k++) {
            float4 a = *(const float4*)&Hs[k][j * 4];
            float4 b = *(const float4*)&Wsh[k][ci * 4];
            float av[4] = {a.x, a.y, a.z, a.w};
            float bv[4] = {b.x, b.y, b.z, b.w};
            #pragma unroll
            for (int r = 0; r < 4; r++)
                #pragma unroll
                for (int c = 0; c < 4; c++)
                    acc[r][c] = fmaf(av[r], bv[c], acc[r][c]);
        }
        __syncthreads();
    }
    #pragma unroll
    for (int r = 0; r < 4; r++) {
        int gn = n0 + j * 4 + r;
        if (gn < NN) {
            #pragma unroll
            for (int c = 0; c < 4; c++)
                out[gn * CCOLS + ci * 4 + c] = acc[r][c] + bp[ci * 4 + c];
        }
    }
}

// ---------------- launch ----------------------------------------------------
extern "C" void kernel_launch(void* const* d_in, const int* in_sizes, int n_in,
                              void* d_out, int out_size) {
    const float* feats = (const float*)d_in[0];
    const int*   src   = (const int*)d_in[1];
    const int*   dst   = (const int*)d_in[2];
    const float* Ws    = (const float*)d_in[3];
    const float* al    = (const float*)d_in[4];
    const float* ar    = (const float*)d_in[5];
    const float* bias  = (const float*)d_in[6];
    const float* gamma = (const float*)d_in[7];
    const float* beta  = (const float*)d_in[8];
    const float* Wp    = (const float*)d_in[9];
    const float* bp    = (const float*)d_in[10];
    float* out = (float*)d_out;

    float* hp;   cudaGetSymbolAddress((void**)&hp, g_hp);
    float* hbuf; cudaGetSymbolAddress((void**)&hbuf, g_hbuf);

    // CSR build (src/dst fixed; rebuilt each call for determinism of work)
    zero_wr_kernel<<<(NN + 255) / 256, 256>>>();
    count_deg_kernel<<<(EE + 255) / 256, 256>>>(dst);
    scan_deg_kernel<<<1, 1024>>>();
    fill_csr_kernel<<<(EE + 255) / 256, 256>>>(src, dst);

    const int gemm_blocks = (NN + 63) / 64;  // 782
    for (int l = 0; l < 2; l++) {
        const float* hin = (l == 0) ? feats : hbuf;
        gemm_nodes_kernel<<<gemm_blocks, 256>>>(hin, Ws + l * 128 * 128, hp);
        elr_kernel<<<NN, 128>>>(hp, al + l * 128, ar + l * 128);
        gat_agg_kernel<<<NN, 128>>>(hp, bias + l * 128, gamma + l * 128,
                                    beta + l * 128, hbuf);
    }
    pred_kernel<<<gemm_blocks, 160>>>(hbuf, Wp, bp, out);
}

// round 2
// speedup vs baseline: 1.5705x; 1.5705x over previous
#include <cuda_runtime.h>

#define NN 50000
#define EE 800000
#define HH 8
#define HD 128
#define CCOLS 40
#define SCAN_NBLK 49   // ceil(50000/1024)

// ---------------- scratch (static device arrays — no runtime allocation) ----
__device__ float g_hp[NN * HD];    // per-layer projected features
__device__ float g_hbuf[NN * HD];  // layer output / next-layer input
__device__ float g_el[NN * HH];
__device__ float g_er[NN * HH];
__device__ int   g_rowptr[NN + 1];
__device__ int   g_wr[NN];
__device__ int   g_csrc[EE];       // src node id per incoming edge, CSR by dst
__device__ int   g_bsum[64];       // per-block partial-scan sums

// ---------------- CSR build ------------------------------------------------
__global__ void zero_wr_kernel() {
    int i = blockIdx.x * blockDim.x + threadIdx.x;
    if (i < NN) g_wr[i] = 0;
}

__global__ void count_deg_kernel(const int* __restrict__ dst) {
    int e = blockIdx.x * blockDim.x + threadIdx.x;
    if (e < EE) atomicAdd(&g_wr[dst[e]], 1);
}

// phase 1: per-block exclusive scan of 1024 degrees; write partial + blocksum
__global__ __launch_bounds__(1024) void scan1_kernel() {
    __shared__ int wsum[32];
    int t = threadIdx.x;
    int lane = t & 31, wid = t >> 5;
    int i = blockIdx.x * 1024 + t;
    int v = (i < NN) ? g_wr[i] : 0;
    int x = v;
    #pragma unroll
    for (int off = 1; off < 32; off <<= 1) {
        int y = __shfl_up_sync(0xFFFFFFFFu, x, off);
        if (lane >= off) x += y;
    }
    if (lane == 31) wsum[wid] = x;
    __syncthreads();
    if (wid == 0) {
        int w = wsum[lane];
        int xw = w;
        #pragma unroll
        for (int off = 1; off < 32; off <<= 1) {
            int y = __shfl_up_sync(0xFFFFFFFFu, xw, off);
            if (lane >= off) xw += y;
        }
        wsum[lane] = xw - w;   // exclusive warp offset
        if (lane == 31) g_bsum[blockIdx.x] = xw;  // block total
    }
    __syncthreads();
    int excl = wsum[wid] + (x - v);
    if (i < NN) g_rowptr[i] = excl;   // partial (within-block) exclusive
}

// phase 2: exclusive scan of the 49 block sums (one warp's worth padded to 64)
__global__ void scan2_kernel() {
    int t = threadIdx.x;  // 64 threads
    int lane = t & 31, wid = t >> 5;
    __shared__ int w0sum;
    int v = (t < SCAN_NBLK) ? g_bsum[t] : 0;
    int x = v;
    #pragma unroll
    for (int off = 1; off < 32; off <<= 1) {
        int y = __shfl_up_sync(0xFFFFFFFFu, x, off);
        if (lane >= off) x += y;
    }
    if (wid == 0 && lane == 31) w0sum = x;
    __syncthreads();
    int excl = x - v + (wid ? w0sum : 0);
    if (t < SCAN_NBLK) g_bsum[t] = excl;
    if (t == 0) g_rowptr[NN] = EE;
}

// phase 3: add block offsets; also init write cursors
__global__ __launch_bounds__(1024) void scan3_kernel() {
    int i = blockIdx.x * 1024 + threadIdx.x;
    if (i < NN) {
        int v = g_rowptr[i] + g_bsum[blockIdx.x];
        g_rowptr[i] = v;
        g_wr[i] = v;
    }
}

__global__ void fill_csr_kernel(const int* __restrict__ src, const int* __restrict__ dst) {
    int e = blockIdx.x * blockDim.x + threadIdx.x;
    if (e < EE) {
        int p = atomicAdd(&g_wr[dst[e]], 1);
        g_csrc[p] = src[e];
    }
}

// ---------------- GEMM: C[M,128] = A[M,128] @ W[128,128] --------------------
__global__ __launch_bounds__(256) void gemm_nodes_kernel(
    const float* __restrict__ A, const float* __restrict__ W, float* __restrict__ C) {
    __shared__ float Ash[32][68];    // A tile transposed: [k][row]
    __shared__ float Wsh[32][128];
    int tid = threadIdx.x;
    int tx = tid & 31;   // cols 4*tx .. 4*tx+3
    int ty = tid >> 5;   // rows ty*8 .. ty*8+7
    int row0 = blockIdx.x << 6;
    float acc[8][4];
    #pragma unroll
    for (int r = 0; r < 8; r++)
        #pragma unroll
        for (int c = 0; c < 4; c++) acc[r][c] = 0.f;

    for (int kc = 0; kc < 128; kc += 32) {
        #pragma unroll
        for (int i = 0; i < 8; i++) {
            int idx = tid + (i << 8);
            int r = idx >> 5;
            int k = idx & 31;
            int gr = row0 + r;
            Ash[k][r] = (gr < NN) ? A[gr * 128 + kc + k] : 0.f;
        }
        #pragma unroll
        for (int i = 0; i < 16; i++) {
            int idx = tid + (i << 8);
            int k = idx >> 7;
            int c = idx & 127;
            Wsh[k][c] = W[(kc + k) * 128 + c];
        }
        __syncthreads();
        #pragma unroll
        for (int k = 0; k < 32; k++) {
            float4 a0 = *(const float4*)&Ash[k][ty * 8];
            float4 a1 = *(const float4*)&Ash[k][ty * 8 + 4];
            float4 b  = *(const float4*)&Wsh[k][tx * 4];
            float av[8] = {a0.x, a0.y, a0.z, a0.w, a1.x, a1.y, a1.z, a1.w};
            float bv[4] = {b.x, b.y, b.z, b.w};
            #pragma unroll
            for (int r = 0; r < 8; r++)
                #pragma unroll
                for (int c = 0; c < 4; c++)
                    acc[r][c] = fmaf(av[r], bv[c], acc[r][c]);
        }
        __syncthreads();
    }
    #pragma unroll
    for (int r = 0; r < 8; r++) {
        int gr = row0 + ty * 8 + r;
        if (gr < NN) {
            float4 o = make_float4(acc[r][0], acc[r][1], acc[r][2], acc[r][3]);
            *(float4*)&C[gr * 128 + tx * 4] = o;
        }
    }
}

// ---------------- per-node attention logits --------------------------------
__global__ __launch_bounds__(128) void elr_kernel(
    const float* __restrict__ hp, const float* __restrict__ al, const float* __restrict__ ar) {
    int n = blockIdx.x;
    int t = threadIdx.x;  // 128; t = h*16 + d
    float v = hp[n * 128 + t];
    float pl = v * al[t];
    float pr = v * ar[t];
    #pragma unroll
    for (int off = 8; off >= 1; off >>= 1) {
        pl += __shfl_down_sync(0xFFFFFFFFu, pl, off, 16);
        pr += __shfl_down_sync(0xFFFFFFFFu, pr, off, 16);
    }
    if ((t & 15) == 0) {
        g_el[n * 8 + (t >> 4)] = pl;
        g_er[n * 8 + (t >> 4)] = pr;
    }
}

// ---------------- fused: edge-softmax aggregate + bias + LN + ReLU ----------
// warp-per-node, float4 per lane, 4-edge software pipelining for MLP.
// softmax max-shift omitted: logits are bounded (|e| < ~6) so exp is safe.
__global__ __launch_bounds__(256) void gat_agg_kernel(
    const float* __restrict__ hp,
    const float* __restrict__ bias, const float* __restrict__ gamma,
    const float* __restrict__ beta, float* __restrict__ hout) {
    int n = blockIdx.x * 8 + (threadIdx.x >> 5);
    if (n >= NN) return;
    int lane = threadIdx.x & 31;
    int h = lane >> 2;                      // head for channels 4*lane..4*lane+3
    float er_h = g_er[n * 8 + h];
    int beg = g_rowptr[n];
    int end = g_rowptr[n + 1];
    const float4* __restrict__ hp4 = (const float4*)hp;

    float ax = 0.f, ay = 0.f, az = 0.f, aw = 0.f, s = 0.f;
    int j = beg;
    for (; j + 4 <= end; j += 4) {
        int s0 = g_csrc[j], s1 = g_csrc[j + 1], s2 = g_csrc[j + 2], s3 = g_csrc[j + 3];
        float e0 = g_el[s0 * 8 + h] + er_h;
        float e1 = g_el[s1 * 8 + h] + er_h;
        float e2 = g_el[s2 * 8 + h] + er_h;
        float e3 = g_el[s3 * 8 + h] + er_h;
        float4 v0 = hp4[s0 * 32 + lane];
        float4 v1 = hp4[s1 * 32 + lane];
        float4 v2 = hp4[s2 * 32 + lane];
        float4 v3 = hp4[s3 * 32 + lane];
        e0 = (e0 > 0.f) ? e0 : 0.2f * e0;
        e1 = (e1 > 0.f) ? e1 : 0.2f * e1;
        e2 = (e2 > 0.f) ? e2 : 0.2f * e2;
        e3 = (e3 > 0.f) ? e3 : 0.2f * e3;
        float w0 = __expf(e0), w1 = __expf(e1), w2 = __expf(e2), w3 = __expf(e3);
        s += (w0 + w1) + (w2 + w3);
        ax = fmaf(w0, v0.x, fmaf(w1, v1.x, fmaf(w2, v2.x, fmaf(w3, v3.x, ax))));
        ay = fmaf(w0, v0.y, fmaf(w1, v1.y, fmaf(w2, v2.y, fmaf(w3, v3.y, ay))));
        az = fmaf(w0, v0.z, fmaf(w1, v1.z, fmaf(w2, v2.z, fmaf(w3, v3.z, az))));
        aw = fmaf(w0, v0.w, fmaf(w1, v1.w, fmaf(w2, v2.w, fmaf(w3, v3.w, aw))));
    }
    for (; j < end; j++) {
        int s0 = g_csrc[j];
        float e0 = g_el[s0 * 8 + h] + er_h;
        e0 = (e0 > 0.f) ? e0 : 0.2f * e0;
        float w0 = __expf(e0);
        float4 v0 = hp4[s0 * 32 + lane];
        s += w0;
        ax = fmaf(w0, v0.x, ax);
        ay = fmaf(w0, v0.y, ay);
        az = fmaf(w0, v0.z, az);
        aw = fmaf(w0, v0.w, aw);
    }

    float inv = 1.f / (s + 1e-16f);
    float4 b4  = ((const float4*)bias)[lane];
    float4 g4  = ((const float4*)gamma)[lane];
    float4 be4 = ((const float4*)beta)[lane];
    float ox = fmaf(ax, inv, b4.x);
    float oy = fmaf(ay, inv, b4.y);
    float oz = fmaf(az, inv, b4.z);
    float ow = fmaf(aw, inv, b4.w);

    // LayerNorm over 128 channels — pure warp shuffles
    float sum = (ox + oy) + (oz + ow);
    #pragma unroll
    for (int off = 16; off >= 1; off >>= 1) sum += __shfl_xor_sync(0xFFFFFFFFu, sum, off);
    float mu = sum * 0.0078125f;
    float dx = ox - mu, dy = oy - mu, dz = oz - mu, dw = ow - mu;
    float sq = (dx * dx + dy * dy) + (dz * dz + dw * dw);
    #pragma unroll
    for (int off = 16; off >= 1; off >>= 1) sq += __shfl_xor_sync(0xFFFFFFFFu, sq, off);
    float rstd = rsqrtf(sq * 0.0078125f + 1e-5f);
    float4 o;
    o.x = fmaxf(fmaf(dx * rstd, g4.x, be4.x), 0.f);
    o.y = fmaxf(fmaf(dy * rstd, g4.y, be4.y), 0.f);
    o.z = fmaxf(fmaf(dz * rstd, g4.z, be4.z), 0.f);
    o.w = fmaxf(fmaf(dw * rstd, g4.w, be4.w), 0.f);
    ((float4*)hout)[n * 32 + lane] = o;
}

// ---------------- final projection: out[N,40] = h[N,128] @ Wp + bp ----------
__global__ __launch_bounds__(160) void pred_kernel(
    const float* __restrict__ hfeat, const float* __restrict__ Wp,
    const float* __restrict__ bp, float* __restrict__ out) {
    __shared__ float Hs[64][68];   // [k][node], K-chunk 64
    __shared__ float Wsh[64][40];
    int tid = threadIdx.x;
    int ci = tid % 10;      // cols 4*ci .. 4*ci+3
    int j  = tid / 10;      // nodes j*4 .. j*4+3
    int n0 = blockIdx.x << 6;
    float acc[4][4];
    #pragma unroll
    for (int r = 0; r < 4; r++)
        #pragma unroll
        for (int c = 0; c < 4; c++) acc[r][c] = 0.f;

    for (int kc = 0; kc < 128; kc += 64) {
        for (int idx = tid; idx < 64 * 64; idx += 160) {
            int n = idx >> 6;
            int k = idx & 63;
            int gn = n0 + n;
            Hs[k][n] = (gn < NN) ? hfeat[gn * 128 + kc + k] : 0.f;
        }
        for (int idx = tid; idx < 64 * 40; idx += 160) {
            int k = idx / 40;
            int c = idx - k * 40;
            Wsh[k][c] = Wp[(kc + k) * 40 + c];
        }
        __syncthreads();
        #pragma unroll
        for (int k = 0; k < 64; k++) {
            float4 a = *(const float4*)&Hs[k][j * 4];
            float4 b = *(const float4*)&Wsh[k][ci * 4];
            float av[4] = {a.x, a.y, a.z, a.w};
            float bv[4] = {b.x, b.y, b.z, b.w};
            #pragma unroll
            for (int r = 0; r < 4; r++)
                #pragma unroll
                for (int c = 0; c < 4; c++)
                    acc[r][c] = fmaf(av[r], bv[c], acc[r][c]);
        }
        __syncthreads();
    }
    #pragma unroll
    for (int r = 0; r < 4; r++) {
        int gn = n0 + j * 4 + r;
        if (gn < NN) {
            #pragma unroll
            for (int c = 0; c < 4; c++)
                out[gn * CCOLS + ci * 4 + c] = acc[r][c] + bp[ci * 4 + c];
        }
    }
}

// ---------------- launch ----------------------------------------------------
extern "C" void kernel_launch(void* const* d_in, const int* in_sizes, int n_in,
                              void* d_out, int out_size) {
    const float* feats = (const float*)d_in[0];
    const int*   src   = (const int*)d_in[1];
    const int*   dst   = (const int*)d_in[2];
    const float* Ws    = (const float*)d_in[3];
    const float* al    = (const float*)d_in[4];
    const float* ar    = (const float*)d_in[5];
    const float* bias  = (const float*)d_in[6];
    const float* gamma = (const float*)d_in[7];
    const float* beta  = (const float*)d_in[8];
    const float* Wp    = (const float*)d_in[9];
    const float* bp    = (const float*)d_in[10];
    float* out = (float*)d_out;

    float* hp;   cudaGetSymbolAddress((void**)&hp, g_hp);
    float* hbuf; cudaGetSymbolAddress((void**)&hbuf, g_hbuf);

    // CSR build
    zero_wr_kernel<<<(NN + 255) / 256, 256>>>();
    count_deg_kernel<<<(EE + 255) / 256, 256>>>(dst);
    scan1_kernel<<<SCAN_NBLK, 1024>>>();
    scan2_kernel<<<1, 64>>>();
    scan3_kernel<<<SCAN_NBLK, 1024>>>();
    fill_csr_kernel<<<(EE + 255) / 256, 256>>>(src, dst);

    const int gemm_blocks = (NN + 63) / 64;  // 782
    for (int l = 0; l < 2; l++) {
        const float* hin = (l == 0) ? feats : hbuf;
        gemm_nodes_kernel<<<gemm_blocks, 256>>>(hin, Ws + l * 128 * 128, hp);
        elr_kernel<<<NN, 128>>>(hp, al + l * 128, ar + l * 128);
        gat_agg_kernel<<<(NN + 7) / 8, 256>>>(hp, bias + l * 128, gamma + l * 128,
                                              beta + l * 128, hbuf);
    }
    pred_kernel<<<gemm_blocks, 160>>>(hbuf, Wp, bp, out);
}

// round 3
// speedup vs baseline: 1.9560x; 1.2454x over previous
#include <cuda_runtime.h>
#include <cstdint>

#define NN 50000
#define EE 800000
#define HH 8
#define HD 128
#define CCOLS 40
#define SCAN_NBLK 49   // ceil(50000/1024)

// ---------------- scratch (static device arrays — no runtime allocation) ----
__device__ float g_hp[NN * HD];    // per-layer projected features
__device__ float g_hbuf[NN * HD];  // layer output / next-layer input
__device__ float g_el[NN * HH];
__device__ float g_er[NN * HH];
__device__ int   g_rowptr[NN + 1];
__device__ int   g_wr[NN];
__device__ int   g_csrc[EE];       // src node id per incoming edge, CSR by dst
__device__ int   g_bsum[64];       // per-block partial-scan sums

// ---------------- CSR build ------------------------------------------------
__global__ void zero_wr_kernel() {
    int i = blockIdx.x * blockDim.x + threadIdx.x;
    if (i < NN) g_wr[i] = 0;
}

__global__ void count_deg_kernel(const int* __restrict__ dst) {
    int e = blockIdx.x * blockDim.x + threadIdx.x;
    if (e < EE) atomicAdd(&g_wr[dst[e]], 1);
}

// phase 1: per-block exclusive scan of 1024 degrees; write partial + blocksum
__global__ __launch_bounds__(1024) void scan1_kernel() {
    __shared__ int wsum[32];
    int t = threadIdx.x;
    int lane = t & 31, wid = t >> 5;
    int i = blockIdx.x * 1024 + t;
    int v = (i < NN) ? g_wr[i] : 0;
    int x = v;
    #pragma unroll
    for (int off = 1; off < 32; off <<= 1) {
        int y = __shfl_up_sync(0xFFFFFFFFu, x, off);
        if (lane >= off) x += y;
    }
    if (lane == 31) wsum[wid] = x;
    __syncthreads();
    if (wid == 0) {
        int w = wsum[lane];
        int xw = w;
        #pragma unroll
        for (int off = 1; off < 32; off <<= 1) {
            int y = __shfl_up_sync(0xFFFFFFFFu, xw, off);
            if (lane >= off) xw += y;
        }
        wsum[lane] = xw - w;   // exclusive warp offset
        if (lane == 31) g_bsum[blockIdx.x] = xw;  // block total
    }
    __syncthreads();
    int excl = wsum[wid] + (x - v);
    if (i < NN) g_rowptr[i] = excl;   // partial (within-block) exclusive
}

// phase 2: exclusive scan of the 49 block sums
__global__ void scan2_kernel() {
    int t = threadIdx.x;  // 64 threads
    int lane = t & 31, wid = t >> 5;
    __shared__ int w0sum;
    int v = (t < SCAN_NBLK) ? g_bsum[t] : 0;
    int x = v;
    #pragma unroll
    for (int off = 1; off < 32; off <<= 1) {
        int y = __shfl_up_sync(0xFFFFFFFFu, x, off);
        if (lane >= off) x += y;
    }
    if (wid == 0 && lane == 31) w0sum = x;
    __syncthreads();
    int excl = x - v + (wid ? w0sum : 0);
    if (t < SCAN_NBLK) g_bsum[t] = excl;
    if (t == 0) g_rowptr[NN] = EE;
}

// phase 3: add block offsets; also init write cursors
__global__ __launch_bounds__(1024) void scan3_kernel() {
    int i = blockIdx.x * 1024 + threadIdx.x;
    if (i < NN) {
        int v = g_rowptr[i] + g_bsum[blockIdx.x];
        g_rowptr[i] = v;
        g_wr[i] = v;
    }
}

__global__ void fill_csr_kernel(const int* __restrict__ src, const int* __restrict__ dst) {
    int e = blockIdx.x * blockDim.x + threadIdx.x;
    if (e < EE) {
        int p = atomicAdd(&g_wr[dst[e]], 1);
        g_csrc[p] = src[e];
    }
}

// ---------------- TF32 tensor-core GEMM: C[M,128] = A[M,128] @ W[128,128] ----
__device__ __forceinline__ uint32_t f2tf32(float x) {
    uint32_t r;
    asm("cvt.rna.tf32.f32 %0, %1;" : "=r"(r) : "f"(x));
    return r;
}

__device__ __forceinline__ void mma_tf32(float* c, const uint32_t* a,
                                         uint32_t b0, uint32_t b1) {
    asm volatile(
        "mma.sync.aligned.m16n8k8.row.col.f32.tf32.tf32.f32 "
        "{%0,%1,%2,%3}, {%4,%5,%6,%7}, {%8,%9}, {%0,%1,%2,%3};"
        : "+f"(c[0]), "+f"(c[1]), "+f"(c[2]), "+f"(c[3])
        : "r"(a[0]), "r"(a[1]), "r"(a[2]), "r"(a[3]), "r"(b0), "r"(b1));
}

// block: 256 thr = 8 warps in 2(row)x4(col) grid; block tile 64 rows x 128 cols
__global__ __launch_bounds__(256) void gemm_tf32_kernel(
    const float* __restrict__ A, const float* __restrict__ W, float* __restrict__ C) {
    __shared__ uint32_t As[64][36];    // [row][k-in-chunk], pad 4 -> frag reads conflict-free
    __shared__ uint32_t Wsh[32][136];  // [k-in-chunk][col], pad 8 -> frag reads conflict-free
    int tid = threadIdx.x;
    int wid = tid >> 5;
    int lane = tid & 31;
    int g = lane >> 2;       // group id 0..7
    int tig = lane & 3;      // thread in group 0..3
    int warpRow = wid & 1;   // 0..1  (32-row slabs)
    int warpCol = wid >> 1;  // 0..3  (32-col slabs)
    int row0 = blockIdx.x << 6;

    float c[2][4][4];
    #pragma unroll
    for (int sm = 0; sm < 2; sm++)
        #pragma unroll
        for (int sn = 0; sn < 4; sn++)
            #pragma unroll
            for (int q = 0; q < 4; q++) c[sm][sn][q] = 0.f;

    for (int kc = 0; kc < 128; kc += 32) {
        // load A chunk: 64 rows x 32 k
        #pragma unroll
        for (int q = 0; q < 2; q++) {
            int lin = tid + (q << 8);
            int r = lin >> 3;
            int k4 = lin & 7;
            int gr = row0 + r;
            float4 v = (gr < NN) ? *(const float4*)&A[gr * 128 + kc + k4 * 4]
                                 : make_float4(0.f, 0.f, 0.f, 0.f);
            uint32_t* p = &As[r][k4 * 4];
            p[0] = f2tf32(v.x); p[1] = f2tf32(v.y);
            p[2] = f2tf32(v.z); p[3] = f2tf32(v.w);
        }
        // load W chunk: 32 k x 128 cols
        #pragma unroll
        for (int q = 0; q < 4; q++) {
            int lin = tid + (q << 8);
            int k = lin >> 5;
            int c4 = lin & 31;
            float4 v = *(const float4*)&W[(kc + k) * 128 + c4 * 4];
            uint32_t* p = &Wsh[k][c4 * 4];
            p[0] = f2tf32(v.x); p[1] = f2tf32(v.y);
            p[2] = f2tf32(v.z); p[3] = f2tf32(v.w);
        }
        __syncthreads();
        #pragma unroll
        for (int kk = 0; kk < 32; kk += 8) {
            uint32_t a[2][4];
            #pragma unroll
            for (int sm = 0; sm < 2; sm++) {
                int r = warpRow * 32 + sm * 16 + g;
                a[sm][0] = As[r][kk + tig];
                a[sm][1] = As[r + 8][kk + tig];
                a[sm][2] = As[r][kk + tig + 4];
                a[sm][3] = As[r + 8][kk + tig + 4];
            }
            #pragma unroll
            for (int sn = 0; sn < 4; sn++) {
                int cix = warpCol * 32 + sn * 8 + g;
                uint32_t b0 = Wsh[kk + tig][cix];
                uint32_t b1 = Wsh[kk + tig + 4][cix];
                mma_tf32(c[0][sn], a[0], b0, b1);
                mma_tf32(c[1][sn], a[1], b0, b1);
            }
        }
        __syncthreads();
    }
    // epilogue: c0 (row g, col 2t), c1 (row g, col 2t+1), c2/c3 row g+8
    #pragma unroll
    for (int sm = 0; sm < 2; sm++) {
        int rbase = row0 + warpRow * 32 + sm * 16 + g;
        #pragma unroll
        for (int sn = 0; sn < 4; sn++) {
            int col = warpCol * 32 + sn * 8 + tig * 2;
            if (rbase < NN)
                *(float2*)&C[rbase * 128 + col] = make_float2(c[sm][sn][0], c[sm][sn][1]);
            if (rbase + 8 < NN)
                *(float2*)&C[(rbase + 8) * 128 + col] = make_float2(c[sm][sn][2], c[sm][sn][3]);
        }
    }
}

// ---------------- per-node attention logits --------------------------------
__global__ __launch_bounds__(128) void elr_kernel(
    const float* __restrict__ hp, const float* __restrict__ al, const float* __restrict__ ar) {
    int n = blockIdx.x;
    int t = threadIdx.x;  // 128; t = h*16 + d
    float v = hp[n * 128 + t];
    float pl = v * al[t];
    float pr = v * ar[t];
    #pragma unroll
    for (int off = 8; off >= 1; off >>= 1) {
        pl += __shfl_down_sync(0xFFFFFFFFu, pl, off, 16);
        pr += __shfl_down_sync(0xFFFFFFFFu, pr, off, 16);
    }
    if ((t & 15) == 0) {
        g_el[n * 8 + (t >> 4)] = pl;
        g_er[n * 8 + (t >> 4)] = pr;
    }
}

// ---------------- fused: edge-softmax aggregate + bias + LN + ReLU ----------
__global__ __launch_bounds__(256) void gat_agg_kernel(
    const float* __restrict__ hp,
    const float* __restrict__ bias, const float* __restrict__ gamma,
    const float* __restrict__ beta, float* __restrict__ hout) {
    int n = blockIdx.x * 8 + (threadIdx.x >> 5);
    if (n >= NN) return;
    int lane = threadIdx.x & 31;
    int h = lane >> 2;                      // head for channels 4*lane..4*lane+3
    float er_h = g_er[n * 8 + h];
    int beg = g_rowptr[n];
    int end = g_rowptr[n + 1];
    const float4* __restrict__ hp4 = (const float4*)hp;

    float ax = 0.f, ay = 0.f, az = 0.f, aw = 0.f, s = 0.f;
    int j = beg;
    for (; j + 4 <= end; j += 4) {
        int s0 = g_csrc[j], s1 = g_csrc[j + 1], s2 = g_csrc[j + 2], s3 = g_csrc[j + 3];
        float e0 = g_el[s0 * 8 + h] + er_h;
        float e1 = g_el[s1 * 8 + h] + er_h;
        float e2 = g_el[s2 * 8 + h] + er_h;
        float e3 = g_el[s3 * 8 + h] + er_h;
        float4 v0 = hp4[s0 * 32 + lane];
        float4 v1 = hp4[s1 * 32 + lane];
        float4 v2 = hp4[s2 * 32 + lane];
        float4 v3 = hp4[s3 * 32 + lane];
        e0 = (e0 > 0.f) ? e0 : 0.2f * e0;
        e1 = (e1 > 0.f) ? e1 : 0.2f * e1;
        e2 = (e2 > 0.f) ? e2 : 0.2f * e2;
        e3 = (e3 > 0.f) ? e3 : 0.2f * e3;
        float w0 = __expf(e0), w1 = __expf(e1), w2 = __expf(e2), w3 = __expf(e3);
        s += (w0 + w1) + (w2 + w3);
        ax = fmaf(w0, v0.x, fmaf(w1, v1.x, fmaf(w2, v2.x, fmaf(w3, v3.x, ax))));
        ay = fmaf(w0, v0.y, fmaf(w1, v1.y, fmaf(w2, v2.y, fmaf(w3, v3.y, ay))));
        az = fmaf(w0, v0.z, fmaf(w1, v1.z, fmaf(w2, v2.z, fmaf(w3, v3.z, az))));
        aw = fmaf(w0, v0.w, fmaf(w1, v1.w, fmaf(w2, v2.w, fmaf(w3, v3.w, aw))));
    }
    for (; j < end; j++) {
        int s0 = g_csrc[j];
        float e0 = g_el[s0 * 8 + h] + er_h;
        e0 = (e0 > 0.f) ? e0 : 0.2f * e0;
        float w0 = __expf(e0);
        float4 v0 = hp4[s0 * 32 + lane];
        s += w0;
        ax = fmaf(w0, v0.x, ax);
        ay = fmaf(w0, v0.y, ay);
        az = fmaf(w0, v0.z, az);
        aw = fmaf(w0, v0.w, aw);
    }

    float inv = 1.f / (s + 1e-16f);
    float4 b4  = ((const float4*)bias)[lane];
    float4 g4  = ((const float4*)gamma)[lane];
    float4 be4 = ((const float4*)beta)[lane];
    float ox = fmaf(ax, inv, b4.x);
    float oy = fmaf(ay, inv, b4.y);
    float oz = fmaf(az, inv, b4.z);
    float ow = fmaf(aw, inv, b4.w);

    // LayerNorm over 128 channels — pure warp shuffles
    float sum = (ox + oy) + (oz + ow);
    #pragma unroll
    for (int off = 16; off >= 1; off >>= 1) sum += __shfl_xor_sync(0xFFFFFFFFu, sum, off);
    float mu = sum * 0.0078125f;
    float dx = ox - mu, dy = oy - mu, dz = oz - mu, dw = ow - mu;
    float sq = (dx * dx + dy * dy) + (dz * dz + dw * dw);
    #pragma unroll
    for (int off = 16; off >= 1; off >>= 1) sq += __shfl_xor_sync(0xFFFFFFFFu, sq, off);
    float rstd = rsqrtf(sq * 0.0078125f + 1e-5f);
    float4 o;
    o.x = fmaxf(fmaf(dx * rstd, g4.x, be4.x), 0.f);
    o.y = fmaxf(fmaf(dy * rstd, g4.y, be4.y), 0.f);
    o.z = fmaxf(fmaf(dz * rstd, g4.z, be4.z), 0.f);
    o.w = fmaxf(fmaf(dw * rstd, g4.w, be4.w), 0.f);
    ((float4*)hout)[n * 32 + lane] = o;
}

// ---------------- final projection: out[N,40] = h[N,128] @ Wp + bp ----------
__global__ __launch_bounds__(160) void pred_kernel(
    const float* __restrict__ hfeat, const float* __restrict__ Wp,
    const float* __restrict__ bp, float* __restrict__ out) {
    __shared__ float Hs[64][68];   // [k][node], K-chunk 64
    __shared__ float Wsh[64][40];
    int tid = threadIdx.x;
    int ci = tid % 10;      // cols 4*ci .. 4*ci+3
    int j  = tid / 10;      // nodes j*4 .. j*4+3
    int n0 = blockIdx.x << 6;
    float acc[4][4];
    #pragma unroll
    for (int r = 0; r < 4; r++)
        #pragma unroll
        for (int c = 0; c < 4; c++) acc[r][c] = 0.f;

    for (int kc = 0; kc < 128; kc += 64) {
        for (int idx = tid; idx < 64 * 64; idx += 160) {
            int n = idx >> 6;
            int k = idx & 63;
            int gn = n0 + n;
            Hs[k][n] = (gn < NN) ? hfeat[gn * 128 + kc + k] : 0.f;
        }
        for (int idx = tid; idx < 64 * 40; idx += 160) {
            int k = idx / 40;
            int c = idx - k * 40;
            Wsh[k][c] = Wp[(kc + k) * 40 + c];
        }
        __syncthreads();
        #pragma unroll
        for (int k = 0; k < 64; k++) {
            float4 a = *(const float4*)&Hs[k][j * 4];
            float4 b = *(const float4*)&Wsh[k][ci * 4];
            float av[4] = {a.x, a.y, a.z, a.w};
            float bv[4] = {b.x, b.y, b.z, b.w};
            #pragma unroll
            for (int r = 0; r < 4; r++)
                #pragma unroll
                for (int c = 0; c < 4; c++)
                    acc[r][c] = fmaf(av[r], bv[c], acc[r][c]);
        }
        __syncthreads();
    }
    #pragma unroll
    for (int r = 0; r < 4; r++) {
        int gn = n0 + j * 4 + r;
        if (gn < NN) {
            #pragma unroll
            for (int c = 0; c < 4; c++)
                out[gn * CCOLS + ci * 4 + c] = acc[r][c] + bp[ci * 4 + c];
        }
    }
}

// ---------------- launch ----------------------------------------------------
extern "C" void kernel_launch(void* const* d_in, const int* in_sizes, int n_in,
                              void* d_out, int out_size) {
    const float* feats = (const float*)d_in[0];
    const int*   src   = (const int*)d_in[1];
    const int*   dst   = (const int*)d_in[2];
    const float* Ws    = (const float*)d_in[3];
    const float* al    = (const float*)d_in[4];
    const float* ar    = (const float*)d_in[5];
    const float* bias  = (const float*)d_in[6];
    const float* gamma = (const float*)d_in[7];
    const float* beta  = (const float*)d_in[8];
    const float* Wp    = (const float*)d_in[9];
    const float* bp    = (const float*)d_in[10];
    float* out = (float*)d_out;

    float* hp;   cudaGetSymbolAddress((void**)&hp, g_hp);
    float* hbuf; cudaGetSymbolAddress((void**)&hbuf, g_hbuf);

    // CSR build
    zero_wr_kernel<<<(NN + 255) / 256, 256>>>();
    count_deg_kernel<<<(EE + 255) / 256, 256>>>(dst);
    scan1_kernel<<<SCAN_NBLK, 1024>>>();
    scan2_kernel<<<1, 64>>>();
    scan3_kernel<<<SCAN_NBLK, 1024>>>();
    fill_csr_kernel<<<(EE + 255) / 256, 256>>>(src, dst);

    const int gemm_blocks = (NN + 63) / 64;  // 782
    for (int l = 0; l < 2; l++) {
        const float* hin = (l == 0) ? feats : hbuf;
        gemm_tf32_kernel<<<gemm_blocks, 256>>>(hin, Ws + l * 128 * 128, hp);
        elr_kernel<<<NN, 128>>>(hp, al + l * 128, ar + l * 128);
        gat_agg_kernel<<<(NN + 7) / 8, 256>>>(hp, bias + l * 128, gamma + l * 128,
                                              beta + l * 128, hbuf);
    }
    pred_kernel<<<gemm_blocks, 160>>>(hbuf, Wp, bp, out);
}

// round 4
// speedup vs baseline: 2.5361x; 1.2966x over previous
#include <cuda_runtime.h>
#include <cstdint>

#define NN 50000
#define EE 800000
#define HH 8
#define HD 128
#define CCOLS 40
#define SCAN_NBLK 49   // ceil(50000/1024)

// ---------------- scratch -------------------------------------------------
__device__ float g_hp[NN * HD];
__device__ float g_hbuf[NN * HD];
__device__ float g_el[NN * HH];
__device__ float g_er[NN * HH];
__device__ int   g_rowptr[NN + 1];
__device__ int   g_wr[NN];
__device__ int   g_csrc[EE];
__device__ int   g_bsum[64];

// ---------------- CSR build ------------------------------------------------
__global__ void zero_wr_kernel() {
    int i = blockIdx.x * blockDim.x + threadIdx.x;
    if (i < NN) g_wr[i] = 0;
}

// 4 edges per thread via int4
__global__ void count_deg_kernel(const int* __restrict__ dst) {
    int e4 = blockIdx.x * blockDim.x + threadIdx.x;
    if (e4 * 4 < EE) {
        int4 d = ((const int4*)dst)[e4];
        atomicAdd(&g_wr[d.x], 1);
        atomicAdd(&g_wr[d.y], 1);
        atomicAdd(&g_wr[d.z], 1);
        atomicAdd(&g_wr[d.w], 1);
    }
}

__global__ __launch_bounds__(1024) void scan1_kernel() {
    __shared__ int wsum[32];
    int t = threadIdx.x;
    int lane = t & 31, wid = t >> 5;
    int i = blockIdx.x * 1024 + t;
    int v = (i < NN) ? g_wr[i] : 0;
    int x = v;
    #pragma unroll
    for (int off = 1; off < 32; off <<= 1) {
        int y = __shfl_up_sync(0xFFFFFFFFu, x, off);
        if (lane >= off) x += y;
    }
    if (lane == 31) wsum[wid] = x;
    __syncthreads();
    if (wid == 0) {
        int w = wsum[lane];
        int xw = w;
        #pragma unroll
        for (int off = 1; off < 32; off <<= 1) {
            int y = __shfl_up_sync(0xFFFFFFFFu, xw, off);
            if (lane >= off) xw += y;
        }
        wsum[lane] = xw - w;
        if (lane == 31) g_bsum[blockIdx.x] = xw;
    }
    __syncthreads();
    int excl = wsum[wid] + (x - v);
    if (i < NN) g_rowptr[i] = excl;
}

__global__ void scan2_kernel() {
    int t = threadIdx.x;  // 64
    int lane = t & 31, wid = t >> 5;
    __shared__ int w0sum;
    int v = (t < SCAN_NBLK) ? g_bsum[t] : 0;
    int x = v;
    #pragma unroll
    for (int off = 1; off < 32; off <<= 1) {
        int y = __shfl_up_sync(0xFFFFFFFFu, x, off);
        if (lane >= off) x += y;
    }
    if (wid == 0 && lane == 31) w0sum = x;
    __syncthreads();
    int excl = x - v + (wid ? w0sum : 0);
    if (t < SCAN_NBLK) g_bsum[t] = excl;
    if (t == 0) g_rowptr[NN] = EE;
}

__global__ __launch_bounds__(1024) void scan3_kernel() {
    int i = blockIdx.x * 1024 + threadIdx.x;
    if (i < NN) {
        int v = g_rowptr[i] + g_bsum[blockIdx.x];
        g_rowptr[i] = v;
        g_wr[i] = v;
    }
}

__global__ void fill_csr_kernel(const int* __restrict__ src, const int* __restrict__ dst) {
    int e4 = blockIdx.x * blockDim.x + threadIdx.x;
    if (e4 * 4 < EE) {
        int4 d = ((const int4*)dst)[e4];
        int4 s = ((const int4*)src)[e4];
        g_csrc[atomicAdd(&g_wr[d.x], 1)] = s.x;
        g_csrc[atomicAdd(&g_wr[d.y], 1)] = s.y;
        g_csrc[atomicAdd(&g_wr[d.z], 1)] = s.z;
        g_csrc[atomicAdd(&g_wr[d.w], 1)] = s.w;
    }
}

// ---------------- TF32 GEMM + fused el/er epilogue --------------------------
__device__ __forceinline__ uint32_t f2tf32(float x) {
    uint32_t r;
    asm("cvt.rna.tf32.f32 %0, %1;" : "=r"(r) : "f"(x));
    return r;
}

__device__ __forceinline__ void mma_tf32(float* c, const uint32_t* a,
                                         uint32_t b0, uint32_t b1) {
    asm volatile(
        "mma.sync.aligned.m16n8k8.row.col.f32.tf32.tf32.f32 "
        "{%0,%1,%2,%3}, {%4,%5,%6,%7}, {%8,%9}, {%0,%1,%2,%3};"
        : "+f"(c[0]), "+f"(c[1]), "+f"(c[2]), "+f"(c[3])
        : "r"(a[0]), "r"(a[1]), "r"(a[2]), "r"(a[3]), "r"(b0), "r"(b1));
}

// block: 256 thr = 8 warps in 2(row)x4(col) grid; tile 64 rows x 128 cols.
// epilogue also produces el[n,h], er[n,h]: head h sits inside one warpCol slab,
// so each (row, head) sum is owned by one warp -> shfl over tig group, no atomics.
__global__ __launch_bounds__(256) void gemm_tf32_kernel(
    const float* __restrict__ A, const float* __restrict__ W, float* __restrict__ C,
    const float* __restrict__ al, const float* __restrict__ ar) {
    __shared__ uint32_t As[64][36];
    __shared__ uint32_t Wsh[32][136];
    __shared__ float s_el[64][8];
    __shared__ float s_er[64][8];
    int tid = threadIdx.x;
    int wid = tid >> 5;
    int lane = tid & 31;
    int g = lane >> 2;
    int tig = lane & 3;
    int warpRow = wid & 1;
    int warpCol = wid >> 1;
    int row0 = blockIdx.x << 6;

    float c[2][4][4];
    #pragma unroll
    for (int sm = 0; sm < 2; sm++)
        #pragma unroll
        for (int sn = 0; sn < 4; sn++)
            #pragma unroll
            for (int q = 0; q < 4; q++) c[sm][sn][q] = 0.f;

    for (int kc = 0; kc < 128; kc += 32) {
        #pragma unroll
        for (int q = 0; q < 2; q++) {
            int lin = tid + (q << 8);
            int r = lin >> 3;
            int k4 = lin & 7;
            int gr = row0 + r;
            float4 v = (gr < NN) ? *(const float4*)&A[gr * 128 + kc + k4 * 4]
                                 : make_float4(0.f, 0.f, 0.f, 0.f);
            uint32_t* p = &As[r][k4 * 4];
            p[0] = f2tf32(v.x); p[1] = f2tf32(v.y);
            p[2] = f2tf32(v.z); p[3] = f2tf32(v.w);
        }
        #pragma unroll
        for (int q = 0; q < 4; q++) {
            int lin = tid + (q << 8);
            int k = lin >> 5;
            int c4 = lin & 31;
            float4 v = *(const float4*)&W[(kc + k) * 128 + c4 * 4];
            uint32_t* p = &Wsh[k][c4 * 4];
            p[0] = f2tf32(v.x); p[1] = f2tf32(v.y);
            p[2] = f2tf32(v.z); p[3] = f2tf32(v.w);
        }
        __syncthreads();
        #pragma unroll
        for (int kk = 0; kk < 32; kk += 8) {
            uint32_t a[2][4];
            #pragma unroll
            for (int sm = 0; sm < 2; sm++) {
                int r = warpRow * 32 + sm * 16 + g;
                a[sm][0] = As[r][kk + tig];
                a[sm][1] = As[r + 8][kk + tig];
                a[sm][2] = As[r][kk + tig + 4];
                a[sm][3] = As[r + 8][kk + tig + 4];
            }
            #pragma unroll
            for (int sn = 0; sn < 4; sn++) {
                int cix = warpCol * 32 + sn * 8 + g;
                uint32_t b0 = Wsh[kk + tig][cix];
                uint32_t b1 = Wsh[kk + tig + 4][cix];
                mma_tf32(c[0][sn], a[0], b0, b1);
                mma_tf32(c[1][sn], a[1], b0, b1);
            }
        }
        __syncthreads();
    }

    // ---- store C + compute el/er partials ----
    float alr[4][2], arr[4][2];
    #pragma unroll
    for (int sn = 0; sn < 4; sn++) {
        int col = warpCol * 32 + sn * 8 + tig * 2;
        alr[sn][0] = al[col];     alr[sn][1] = al[col + 1];
        arr[sn][0] = ar[col];     arr[sn][1] = ar[col + 1];
    }
    #pragma unroll
    for (int sm = 0; sm < 2; sm++) {
        int rbase = row0 + warpRow * 32 + sm * 16 + g;
        #pragma unroll
        for (int sn = 0; sn < 4; sn++) {
            int col = warpCol * 32 + sn * 8 + tig * 2;
            if (rbase < NN)
                *(float2*)&C[rbase * 128 + col] = make_float2(c[sm][sn][0], c[sm][sn][1]);
            if (rbase + 8 < NN)
                *(float2*)&C[(rbase + 8) * 128 + col] = make_float2(c[sm][sn][2], c[sm][sn][3]);
        }
        // per-thread partials: [hh][ro]  (hh = head pair half, ro = row offset 0/8)
        #pragma unroll
        for (int hh = 0; hh < 2; hh++) {
            #pragma unroll
            for (int ro = 0; ro < 2; ro++) {
                float pel = 0.f, per = 0.f;
                #pragma unroll
                for (int sni = 0; sni < 2; sni++) {
                    int sn = hh * 2 + sni;
                    #pragma unroll
                    for (int qq = 0; qq < 2; qq++) {
                        float cv = c[sm][sn][ro * 2 + qq];
                        pel = fmaf(cv, alr[sn][qq], pel);
                        per = fmaf(cv, arr[sn][qq], per);
                    }
                }
                // reduce across tig group (lanes g*4 + 0..3)
                pel += __shfl_xor_sync(0xFFFFFFFFu, pel, 1);
                pel += __shfl_xor_sync(0xFFFFFFFFu, pel, 2);
                per += __shfl_xor_sync(0xFFFFFFFFu, per, 1);
                per += __shfl_xor_sync(0xFFFFFFFFu, per, 2);
                if (tig == 0) {
                    int r = warpRow * 32 + sm * 16 + g + ro * 8;
                    int h = warpCol * 2 + hh;
                    s_el[r][h] = pel;
                    s_er[r][h] = per;
                }
            }
        }
    }
    __syncthreads();
    #pragma unroll
    for (int q = 0; q < 2; q++) {
        int idx = tid + (q << 8);          // 512 values
        int r = idx >> 3, h = idx & 7;
        if (row0 + r < NN) {
            g_el[(row0 + r) * 8 + h] = s_el[r][h];
            g_er[(row0 + r) * 8 + h] = s_er[r][h];
        }
    }
}

// ---------------- fused: edge-softmax aggregate + bias + LN + ReLU ----------
__global__ __launch_bounds__(256) void gat_agg_kernel(
    const float* __restrict__ hp,
    const float* __restrict__ bias, const float* __restrict__ gamma,
    const float* __restrict__ beta, float* __restrict__ hout) {
    int n = blockIdx.x * 8 + (threadIdx.x >> 5);
    if (n >= NN) return;
    int lane = threadIdx.x & 31;
    int h = lane >> 2;
    float er_h = g_er[n * 8 + h];
    int beg = g_rowptr[n];
    int end = g_rowptr[n + 1];
    const float4* __restrict__ hp4 = (const float4*)hp;

    float ax = 0.f, ay = 0.f, az = 0.f, aw = 0.f, s = 0.f;
    int j = beg;
    // 8 edges in flight
    for (; j + 8 <= end; j += 8) {
        int idx[8];
        #pragma unroll
        for (int u = 0; u < 8; u++) idx[u] = g_csrc[j + u];
        float e[8];
        #pragma unroll
        for (int u = 0; u < 8; u++) e[u] = g_el[idx[u] * 8 + h];
        float4 v[8];
        #pragma unroll
        for (int u = 0; u < 8; u++) v[u] = hp4[idx[u] * 32 + lane];
        #pragma unroll
        for (int u = 0; u < 8; u++) {
            float ee = e[u] + er_h;
            ee = (ee > 0.f) ? ee : 0.2f * ee;
            float w = __expf(ee);
            s += w;
            ax = fmaf(w, v[u].x, ax);
            ay = fmaf(w, v[u].y, ay);
            az = fmaf(w, v[u].z, az);
            aw = fmaf(w, v[u].w, aw);
        }
    }
    for (; j + 4 <= end; j += 4) {
        int idx[4];
        #pragma unroll
        for (int u = 0; u < 4; u++) idx[u] = g_csrc[j + u];
        float e[4];
        #pragma unroll
        for (int u = 0; u < 4; u++) e[u] = g_el[idx[u] * 8 + h];
        float4 v[4];
        #pragma unroll
        for (int u = 0; u < 4; u++) v[u] = hp4[idx[u] * 32 + lane];
        #pragma unroll
        for (int u = 0; u < 4; u++) {
            float ee = e[u] + er_h;
            ee = (ee > 0.f) ? ee : 0.2f * ee;
            float w = __expf(ee);
            s += w;
            ax = fmaf(w, v[u].x, ax);
            ay = fmaf(w, v[u].y, ay);
            az = fmaf(w, v[u].z, az);
            aw = fmaf(w, v[u].w, aw);
        }
    }
    for (; j < end; j++) {
        int s0 = g_csrc[j];
        float e0 = g_el[s0 * 8 + h] + er_h;
        e0 = (e0 > 0.f) ? e0 : 0.2f * e0;
        float w0 = __expf(e0);
        float4 v0 = hp4[s0 * 32 + lane];
        s += w0;
        ax = fmaf(w0, v0.x, ax);
        ay = fmaf(w0, v0.y, ay);
        az = fmaf(w0, v0.z, az);
        aw = fmaf(w0, v0.w, aw);
    }

    float inv = 1.f / (s + 1e-16f);
    float4 b4  = ((const float4*)bias)[lane];
    float4 g4  = ((const float4*)gamma)[lane];
    float4 be4 = ((const float4*)beta)[lane];
    float ox = fmaf(ax, inv, b4.x);
    float oy = fmaf(ay, inv, b4.y);
    float oz = fmaf(az, inv, b4.z);
    float ow = fmaf(aw, inv, b4.w);

    float sum = (ox + oy) + (oz + ow);
    #pragma unroll
    for (int off = 16; off >= 1; off >>= 1) sum += __shfl_xor_sync(0xFFFFFFFFu, sum, off);
    float mu = sum * 0.0078125f;
    float dx = ox - mu, dy = oy - mu, dz = oz - mu, dw = ow - mu;
    float sq = (dx * dx + dy * dy) + (dz * dz + dw * dw);
    #pragma unroll
    for (int off = 16; off >= 1; off >>= 1) sq += __shfl_xor_sync(0xFFFFFFFFu, sq, off);
    float rstd = rsqrtf(sq * 0.0078125f + 1e-5f);
    float4 o;
    o.x = fmaxf(fmaf(dx * rstd, g4.x, be4.x), 0.f);
    o.y = fmaxf(fmaf(dy * rstd, g4.y, be4.y), 0.f);
    o.z = fmaxf(fmaf(dz * rstd, g4.z, be4.z), 0.f);
    o.w = fmaxf(fmaf(dw * rstd, g4.w, be4.w), 0.f);
    ((float4*)hout)[n * 32 + lane] = o;
}

// ---------------- final projection: out[N,40] = h[N,128] @ Wp + bp ----------
__global__ __launch_bounds__(160) void pred_kernel(
    const float* __restrict__ hfeat, const float* __restrict__ Wp,
    const float* __restrict__ bp, float* __restrict__ out) {
    __shared__ float Hs[64][68];
    __shared__ float Wsh[64][40];
    int tid = threadIdx.x;
    int ci = tid % 10;
    int j  = tid / 10;
    int n0 = blockIdx.x << 6;
    float acc[4][4];
    #pragma unroll
    for (int r = 0; r < 4; r++)
        #pragma unroll
        for (int c = 0; c < 4; c++) acc[r][c] = 0.f;

    for (int kc = 0; kc < 128; kc += 64) {
        for (int idx = tid; idx < 64 * 64; idx += 160) {
            int n = idx >> 6;
            int k = idx & 63;
            int gn = n0 + n;
            Hs[k][n] = (gn < NN) ? hfeat[gn * 128 + kc + k] : 0.f;
        }
        for (int idx = tid; idx < 64 * 40; idx += 160) {
            int k = idx / 40;
            int c = idx - k * 40;
            Wsh[k][c] = Wp[(kc + k) * 40 + c];
        }
        __syncthreads();
        #pragma unroll
        for (int k = 0; k < 64; k++) {
            float4 a = *(const float4*)&Hs[k][j * 4];
            float4 b = *(const float4*)&Wsh[k][ci * 4];
            float av[4] = {a.x, a.y, a.z, a.w};
            float bv[4] = {b.x, b.y, b.z, b.w};
            #pragma unroll
            for (int r = 0; r < 4; r++)
                #pragma unroll
                for (int c = 0; c < 4; c++)
                    acc[r][c] = fmaf(av[r], bv[c], acc[r][c]);
        }
        __syncthreads();
    }
    #pragma unroll
    for (int r = 0; r < 4; r++) {
        int gn = n0 + j * 4 + r;
        if (gn < NN) {
            #pragma unroll
            for (int c = 0; c < 4; c++)
                out[gn * CCOLS + ci * 4 + c] = acc[r][c] + bp[ci * 4 + c];
        }
    }
}

// ---------------- launch ----------------------------------------------------
extern "C" void kernel_launch(void* const* d_in, const int* in_sizes, int n_in,
                              void* d_out, int out_size) {
    const float* feats = (const float*)d_in[0];
    const int*   src   = (const int*)d_in[1];
    const int*   dst   = (const int*)d_in[2];
    const float* Ws    = (const float*)d_in[3];
    const float* al    = (const float*)d_in[4];
    const float* ar    = (const float*)d_in[5];
    const float* bias  = (const float*)d_in[6];
    const float* gamma = (const float*)d_in[7];
    const float* beta  = (const float*)d_in[8];
    const float* Wp    = (const float*)d_in[9];
    const float* bp    = (const float*)d_in[10];
    float* out = (float*)d_out;

    float* hp;   cudaGetSymbolAddress((void**)&hp, g_hp);
    float* hbuf; cudaGetSymbolAddress((void**)&hbuf, g_hbuf);

    zero_wr_kernel<<<(NN + 255) / 256, 256>>>();
    count_deg_kernel<<<(EE / 4 + 255) / 256, 256>>>(dst);
    scan1_kernel<<<SCAN_NBLK, 1024>>>();
    scan2_kernel<<<1, 64>>>();
    scan3_kernel<<<SCAN_NBLK, 1024>>>();
    fill_csr_kernel<<<(EE / 4 + 255) / 256, 256>>>(src, dst);

    const int gemm_blocks = (NN + 63) / 64;  // 782
    for (int l = 0; l < 2; l++) {
        const float* hin = (l == 0) ? feats : hbuf;
        gemm_tf32_kernel<<<gemm_blocks, 256>>>(hin, Ws + l * 128 * 128, hp,
                                               al + l * 128, ar + l * 128);
        gat_agg_kernel<<<(NN + 7) / 8, 256>>>(hp, bias + l * 128, gamma + l * 128,
                                              beta + l * 128, hbuf);
    }
    pred_kernel<<<gemm_blocks, 160>>>(hbuf, Wp, bp, out);
}